// round 5
// baseline (speedup 1.0000x reference)
#include <cuda_runtime.h>
#include <cuda_bf16.h>
#include <cstdint>

// Content-addressed select: out = cached_outputs[idx] where idx = first
// fingerprint row equal to x[0..3], else 0. Pure HBM stream copy:
// 256 MiB read + 256 MiB write. DRAM-roofline bound.
//
// R5: config pinned to R1 (8192 blk x 256 thr x ITERS 8, grid-strided,
// __ldcs reads — best kernel time 78.8us). Single change: stores use the
// DEFAULT write-back policy instead of __stcs, letting L2 batch dirty-line
// drains to DRAM (fewer R/W bus turnarounds).

static constexpr long long SLAB_ELEMS = 16384LL * 4096LL;   // 67,108,864 floats
static constexpr long long N4         = SLAB_ELEMS / 4;     // 16,777,216 float4
static constexpr int       N_CASES    = 6;

static constexpr int THREADS = 256;
static constexpr int ITERS   = 8;                             // float4 per thread
static constexpr int BLOCKS  = (int)(N4 / ((long long)ITERS * THREADS)); // 8192
static_assert((long long)BLOCKS * ITERS * THREADS == N4, "exact cover");

__device__ __forceinline__ int select_idx(const float* __restrict__ x,
                                          const float* __restrict__ fp) {
    // Probe = first 4 floats of x. Broadcast loads — L2 hit for all threads.
    const float p0 = __ldg(&x[0]);
    const float p1 = __ldg(&x[1]);
    const float p2 = __ldg(&x[2]);
    const float p3 = __ldg(&x[3]);
    int idx = 0;
    // Reverse iteration: lowest matching index wins (== argmax of first True);
    // no match leaves idx = 0.
    #pragma unroll
    for (int i = N_CASES - 1; i >= 0; --i) {
        const float f0 = __ldg(&fp[i * 4 + 0]);
        const float f1 = __ldg(&fp[i * 4 + 1]);
        const float f2 = __ldg(&fp[i * 4 + 2]);
        const float f3 = __ldg(&fp[i * 4 + 3]);
        if (f0 == p0 && f1 == p1 && f2 == p2 && f3 == p3) idx = i;
    }
    return idx;
}

__global__ __launch_bounds__(THREADS)
void cache_select_copy_kernel(const float* __restrict__ x,
                              const float* __restrict__ fingerprints,
                              const float4* __restrict__ cached,
                              float4* __restrict__ out) {
    const int idx = select_idx(x, fingerprints);
    const float4* __restrict__ src = cached + (long long)idx * N4;

    // Grid-strided: consecutive threads across the grid cover contiguous 16B
    // chunks; iterations stride by the whole grid.
    const long long tid    = (long long)blockIdx.x * THREADS + threadIdx.x;
    const long long stride = (long long)BLOCKS * THREADS;

    // Fixed trip count -> ptxas front-batches 8 independent LDG.128 (MLP=8).
    #pragma unroll
    for (int it = 0; it < ITERS; ++it) {
        const long long i = tid + (long long)it * stride;
        float4 v = __ldcs(&src[i]);   // evict-first read stream (no reuse)
        out[i] = v;                   // default write-back store: L2 batches
                                      // dirty-line drains to DRAM
    }
}

extern "C" void kernel_launch(void* const* d_in, const int* in_sizes, int n_in,
                              void* d_out, int out_size) {
    const float*  x      = (const float*)d_in[0];
    const float*  fps    = (const float*)d_in[1];
    const float4* cached = (const float4*)d_in[2];
    float4*       out    = (float4*)d_out;

    cache_select_copy_kernel<<<BLOCKS, THREADS>>>(x, fps, cached, out);
}

// round 6
// speedup vs baseline: 1.0414x; 1.0414x over previous
#include <cuda_runtime.h>
#include <cuda_bf16.h>
#include <cstdint>

// Content-addressed select: out = cached_outputs[idx] where idx = first
// fingerprint row equal to x[0..3], else 0. Pure HBM stream copy:
// 256 MiB read + 256 MiB write. DRAM-roofline bound.
//
// R6: config pinned to R1 (8192 blk x 256 thr x ITERS 8, grid-strided,
// __ldcs/__stcs — best: 83.6us, kernel 78.8us, DRAM 77.9%). Single change:
// explicit two-phase body — ALL 8 loads buffered into registers, THEN all 8
// stores. Longer same-direction bursts per warp -> fewer DRAM R/W bus
// turnarounds at the memory controllers.

static constexpr long long SLAB_ELEMS = 16384LL * 4096LL;   // 67,108,864 floats
static constexpr long long N4         = SLAB_ELEMS / 4;     // 16,777,216 float4
static constexpr int       N_CASES    = 6;

static constexpr int THREADS = 256;
static constexpr int ITERS   = 8;                             // float4 per thread
static constexpr int BLOCKS  = (int)(N4 / ((long long)ITERS * THREADS)); // 8192
static_assert((long long)BLOCKS * ITERS * THREADS == N4, "exact cover");

__device__ __forceinline__ int select_idx(const float* __restrict__ x,
                                          const float* __restrict__ fp) {
    // Probe = first 4 floats of x. Broadcast loads — L2 hit for all threads.
    const float p0 = __ldg(&x[0]);
    const float p1 = __ldg(&x[1]);
    const float p2 = __ldg(&x[2]);
    const float p3 = __ldg(&x[3]);
    int idx = 0;
    // Reverse iteration: lowest matching index wins (== argmax of first True);
    // no match leaves idx = 0.
    #pragma unroll
    for (int i = N_CASES - 1; i >= 0; --i) {
        const float f0 = __ldg(&fp[i * 4 + 0]);
        const float f1 = __ldg(&fp[i * 4 + 1]);
        const float f2 = __ldg(&fp[i * 4 + 2]);
        const float f3 = __ldg(&fp[i * 4 + 3]);
        if (f0 == p0 && f1 == p1 && f2 == p2 && f3 == p3) idx = i;
    }
    return idx;
}

__global__ __launch_bounds__(THREADS)
void cache_select_copy_kernel(const float* __restrict__ x,
                              const float* __restrict__ fingerprints,
                              const float4* __restrict__ cached,
                              float4* __restrict__ out) {
    const int idx = select_idx(x, fingerprints);
    const float4* __restrict__ src = cached + (long long)idx * N4;

    // Grid-strided: consecutive threads across the grid cover contiguous 16B
    // chunks; iterations stride by the whole grid.
    const long long tid    = (long long)blockIdx.x * THREADS + threadIdx.x;
    const long long stride = (long long)BLOCKS * THREADS;

    // Phase 1: all 8 independent LDG.128 issued back-to-back (MLP=8,
    // one long read burst per warp).
    float4 v[ITERS];
    #pragma unroll
    for (int it = 0; it < ITERS; ++it) {
        v[it] = __ldcs(&src[tid + (long long)it * stride]);
    }

    // Phase 2: all 8 STG.128 back-to-back (one long write burst per warp).
    #pragma unroll
    for (int it = 0; it < ITERS; ++it) {
        __stcs(&out[tid + (long long)it * stride], v[it]);
    }
}

extern "C" void kernel_launch(void* const* d_in, const int* in_sizes, int n_in,
                              void* d_out, int out_size) {
    const float*  x      = (const float*)d_in[0];
    const float*  fps    = (const float*)d_in[1];
    const float4* cached = (const float4*)d_in[2];
    float4*       out    = (float4*)d_out;

    cache_select_copy_kernel<<<BLOCKS, THREADS>>>(x, fps, cached, out);
}

// round 7
// speedup vs baseline: 1.0455x; 1.0039x over previous
#include <cuda_runtime.h>
#include <cuda_bf16.h>
#include <cstdint>

// Content-addressed select: out = cached_outputs[idx] where idx = first
// fingerprint row equal to x[0..3], else 0. Pure HBM stream copy:
// 256 MiB read + 256 MiB write. DRAM-roofline bound.
//
// R7: R6's two-phase burst body (all loads, then all stores) WON
// (82.7us, DRAM 79.2%, occ 64% — occupancy is not binding). This round
// doubles the burst: ITERS 8 -> 16 (16 LDG.128 burst, then 16 STG.128
// burst per warp). Regs ~80-90 -> occ ~50%, which R6 showed is ample.

static constexpr long long SLAB_ELEMS = 16384LL * 4096LL;   // 67,108,864 floats
static constexpr long long N4         = SLAB_ELEMS / 4;     // 16,777,216 float4
static constexpr int       N_CASES    = 6;

static constexpr int THREADS = 256;
static constexpr int ITERS   = 16;                            // float4 per thread
static constexpr int BLOCKS  = (int)(N4 / ((long long)ITERS * THREADS)); // 4096
static_assert((long long)BLOCKS * ITERS * THREADS == N4, "exact cover");

__device__ __forceinline__ int select_idx(const float* __restrict__ x,
                                          const float* __restrict__ fp) {
    // Probe = first 4 floats of x. Broadcast loads — L2 hit for all threads.
    const float p0 = __ldg(&x[0]);
    const float p1 = __ldg(&x[1]);
    const float p2 = __ldg(&x[2]);
    const float p3 = __ldg(&x[3]);
    int idx = 0;
    // Reverse iteration: lowest matching index wins (== argmax of first True);
    // no match leaves idx = 0.
    #pragma unroll
    for (int i = N_CASES - 1; i >= 0; --i) {
        const float f0 = __ldg(&fp[i * 4 + 0]);
        const float f1 = __ldg(&fp[i * 4 + 1]);
        const float f2 = __ldg(&fp[i * 4 + 2]);
        const float f3 = __ldg(&fp[i * 4 + 3]);
        if (f0 == p0 && f1 == p1 && f2 == p2 && f3 == p3) idx = i;
    }
    return idx;
}

__global__ __launch_bounds__(THREADS)
void cache_select_copy_kernel(const float* __restrict__ x,
                              const float* __restrict__ fingerprints,
                              const float4* __restrict__ cached,
                              float4* __restrict__ out) {
    const int idx = select_idx(x, fingerprints);
    const float4* __restrict__ src = cached + (long long)idx * N4;

    // Grid-strided: consecutive threads across the grid cover contiguous 16B
    // chunks; iterations stride by the whole grid.
    const long long tid    = (long long)blockIdx.x * THREADS + threadIdx.x;
    const long long stride = (long long)BLOCKS * THREADS;

    // Phase 1: 16 independent LDG.128 issued back-to-back (one long read
    // burst per warp).
    float4 v[ITERS];
    #pragma unroll
    for (int it = 0; it < ITERS; ++it) {
        v[it] = __ldcs(&src[tid + (long long)it * stride]);
    }

    // Phase 2: 16 STG.128 back-to-back (one long write burst per warp).
    #pragma unroll
    for (int it = 0; it < ITERS; ++it) {
        __stcs(&out[tid + (long long)it * stride], v[it]);
    }
}

extern "C" void kernel_launch(void* const* d_in, const int* in_sizes, int n_in,
                              void* d_out, int out_size) {
    const float*  x      = (const float*)d_in[0];
    const float*  fps    = (const float*)d_in[1];
    const float4* cached = (const float4*)d_in[2];
    float4*       out    = (float4*)d_out;

    cache_select_copy_kernel<<<BLOCKS, THREADS>>>(x, fps, cached, out);
}